// round 1
// baseline (speedup 1.0000x reference)
#include <cuda_runtime.h>
#include <cuda_bf16.h>
#include <math_constants.h>

// Problem constants (fixed shapes from the reference)
#define B_   8
#define C_   21
#define H_   512
#define W_   512
#define HW_  (H_ * W_)           // 262144 = 2^18
#define HW_SHIFT 18
#define NPIX (B_ * HW_)          // 2097152
#define MAX_M 0.5f
#define S_    30.0f

// Scratch state (device globals — no allocations allowed)
__device__ float  g_counts[C_];
__device__ float  g_mlist[C_];
__device__ double g_loss;

// ---------------------------------------------------------------------------
// Kernel 0: zero scratch (must run every launch; graph replays this)
// ---------------------------------------------------------------------------
__global__ void init_kernel() {
    int t = threadIdx.x;
    if (t < C_) g_counts[t] = 0.0f;
    if (t == C_) g_loss = 0.0;
}

// ---------------------------------------------------------------------------
// Kernel 1: per-class pixel counts (histogram over 2M int32 labels)
// ---------------------------------------------------------------------------
__global__ __launch_bounds__(256) void hist_kernel(const int* __restrict__ target) {
    __shared__ int sh[C_];
    if (threadIdx.x < C_) sh[threadIdx.x] = 0;
    __syncthreads();

    const int4* t4 = reinterpret_cast<const int4*>(target);
    int n4 = NPIX / 4;
    for (int i = blockIdx.x * blockDim.x + threadIdx.x; i < n4;
         i += gridDim.x * blockDim.x) {
        int4 v = t4[i];
        atomicAdd(&sh[v.x], 1);
        atomicAdd(&sh[v.y], 1);
        atomicAdd(&sh[v.z], 1);
        atomicAdd(&sh[v.w], 1);
    }
    __syncthreads();
    if (threadIdx.x < C_) {
        int c = sh[threadIdx.x];
        if (c) atomicAdd(&g_counts[threadIdx.x], (float)c);
    }
}

// ---------------------------------------------------------------------------
// Kernel 2: m_list = (counts + 1e-4)^(-1/4), scaled so max(m_list) == MAX_M
// ---------------------------------------------------------------------------
__global__ void mlist_kernel() {
    int t = threadIdx.x;  // 32 threads
    float mi = 0.0f;
    float m  = -CUDART_INF_F;
    if (t < C_) {
        mi = rsqrtf(sqrtf(g_counts[t] + 1e-4f));
        m  = mi;
    }
#pragma unroll
    for (int o = 16; o > 0; o >>= 1)
        m = fmaxf(m, __shfl_xor_sync(0xffffffffu, m, o));
    if (t < C_) g_mlist[t] = mi * (MAX_M / m);
}

// ---------------------------------------------------------------------------
// Kernel 3: per-pixel LDAM NLL, fused LSE, block reduce, f64 atomic accumulate
// ---------------------------------------------------------------------------
__global__ __launch_bounds__(256) void loss_kernel(const float* __restrict__ pred,
                                                   const int*   __restrict__ target) {
    int n = blockIdx.x * blockDim.x + threadIdx.x;  // exact grid: n < NPIX

    int b  = n >> HW_SHIFT;
    int hw = n & (HW_ - 1);
    const float* base = pred + (size_t)(b * C_) * HW_ + hw;

    int   l = target[n];
    float m = g_mlist[l];

    // Load all 21 channel values; subtract the margin only at the target
    // class. Keep the array statically indexed inside the unrolled loop so
    // it stays in registers (dynamic x[l] would spill to local memory).
    float v[C_];
    float maxv = -CUDART_INF_F;
    float vl   = 0.0f;
#pragma unroll
    for (int c = 0; c < C_; c++) {
        float x = __ldg(base + (size_t)c * HW_);
        if (c == l) x -= m;
        v[c] = x;
        maxv = fmaxf(maxv, x);
        if (c == l) vl = x;
    }

    // z_c = S * v_c; lse = S*maxv + log(sum exp(S*(v_c - maxv)))
    float s = 0.0f;
#pragma unroll
    for (int c = 0; c < C_; c++)
        s += __expf(S_ * (v[c] - maxv));

    float nll = __logf(s) + S_ * (maxv - vl);

    // Warp reduce, then cross-warp via smem, then one f64 atomic per block.
    #pragma unroll
    for (int o = 16; o > 0; o >>= 1)
        nll += __shfl_xor_sync(0xffffffffu, nll, o);

    __shared__ float warp_sums[8];  // 256 threads = 8 warps
    int lane = threadIdx.x & 31;
    int wid  = threadIdx.x >> 5;
    if (lane == 0) warp_sums[wid] = nll;
    __syncthreads();

    if (wid == 0) {
        float x = (lane < 8) ? warp_sums[lane] : 0.0f;
        #pragma unroll
        for (int o = 4; o > 0; o >>= 1)
            x += __shfl_xor_sync(0xffffffffu, x, o);
        if (lane == 0) atomicAdd(&g_loss, (double)x);
    }
}

// ---------------------------------------------------------------------------
// Kernel 4: finalize — mean over all pixels, write f32 scalar
// ---------------------------------------------------------------------------
__global__ void finalize_kernel(float* __restrict__ out) {
    out[0] = (float)(g_loss * (1.0 / (double)NPIX));
}

// ---------------------------------------------------------------------------
extern "C" void kernel_launch(void* const* d_in, const int* in_sizes, int n_in,
                              void* d_out, int out_size) {
    const float* pred   = (const float*)d_in[0];
    const int*   target = (const int*)d_in[1];
    float*       out    = (float*)d_out;

    init_kernel<<<1, 32>>>();
    hist_kernel<<<512, 256>>>(target);
    mlist_kernel<<<1, 32>>>();
    loss_kernel<<<NPIX / 256, 256>>>(pred, target);
    finalize_kernel<<<1, 1>>>(out);
}

// round 2
// speedup vs baseline: 1.0164x; 1.0164x over previous
#include <cuda_runtime.h>
#include <cuda_bf16.h>
#include <math_constants.h>

// Problem constants (fixed shapes from the reference)
#define B_   8
#define C_   21
#define H_   512
#define W_   512
#define HW_  (H_ * W_)           // 262144 = 2^18
#define HW_SHIFT 18
#define NPIX (B_ * HW_)          // 2097152
#define MAX_M 0.5f
#define S_    30.0f

// Scratch state (device globals — no allocations allowed)
__device__ float  g_counts[C_];
__device__ float  g_mlist[C_];
__device__ double g_loss;

// ---------------------------------------------------------------------------
// Kernel 0: zero scratch (must run every launch; graph replays this)
// ---------------------------------------------------------------------------
__global__ void init_kernel() {
    int t = threadIdx.x;
    if (t < C_) g_counts[t] = 0.0f;
    if (t == C_) g_loss = 0.0;
}

// ---------------------------------------------------------------------------
// Kernel 1: per-class pixel counts (histogram over 2M int32 labels)
// ---------------------------------------------------------------------------
__global__ __launch_bounds__(256) void hist_kernel(const int* __restrict__ target) {
    __shared__ int sh[C_];
    if (threadIdx.x < C_) sh[threadIdx.x] = 0;
    __syncthreads();

    const int4* t4 = reinterpret_cast<const int4*>(target);
    int n4 = NPIX / 4;
    for (int i = blockIdx.x * blockDim.x + threadIdx.x; i < n4;
         i += gridDim.x * blockDim.x) {
        int4 v = t4[i];
        atomicAdd(&sh[v.x], 1);
        atomicAdd(&sh[v.y], 1);
        atomicAdd(&sh[v.z], 1);
        atomicAdd(&sh[v.w], 1);
    }
    __syncthreads();
    if (threadIdx.x < C_) {
        int c = sh[threadIdx.x];
        if (c) atomicAdd(&g_counts[threadIdx.x], (float)c);
    }
}

// ---------------------------------------------------------------------------
// Kernel 2: m_list = (counts + 1e-4)^(-1/4), scaled so max(m_list) == MAX_M
// ---------------------------------------------------------------------------
__global__ void mlist_kernel() {
    int t = threadIdx.x;  // 32 threads
    float mi = 0.0f;
    float m  = -CUDART_INF_F;
    if (t < C_) {
        mi = rsqrtf(sqrtf(g_counts[t] + 1e-4f));
        m  = mi;
    }
#pragma unroll
    for (int o = 16; o > 0; o >>= 1)
        m = fmaxf(m, __shfl_xor_sync(0xffffffffu, m, o));
    if (t < C_) g_mlist[t] = mi * (MAX_M / m);
}

// ---------------------------------------------------------------------------
// Kernel 3: per-pixel LDAM NLL, fused LSE, block reduce, f64 atomic accumulate
// ---------------------------------------------------------------------------
__global__ __launch_bounds__(256) void loss_kernel(const float* __restrict__ pred,
                                                   const int*   __restrict__ target) {
    int n = blockIdx.x * blockDim.x + threadIdx.x;  // exact grid: n < NPIX

    int b  = n >> HW_SHIFT;
    int hw = n & (HW_ - 1);
    const float* base = pred + (size_t)(b * C_) * HW_ + hw;

    int   l = target[n];
    float m = g_mlist[l];

    // Load all 21 channel values; subtract the margin only at the target
    // class. Keep the array statically indexed inside the unrolled loop so
    // it stays in registers (dynamic x[l] would spill to local memory).
    float v[C_];
    float maxv = -CUDART_INF_F;
    float vl   = 0.0f;
#pragma unroll
    for (int c = 0; c < C_; c++) {
        float x = __ldg(base + (size_t)c * HW_);
        if (c == l) x -= m;
        v[c] = x;
        maxv = fmaxf(maxv, x);
        if (c == l) vl = x;
    }

    // z_c = S * v_c; lse = S*maxv + log(sum exp(S*(v_c - maxv)))
    float s = 0.0f;
#pragma unroll
    for (int c = 0; c < C_; c++)
        s += __expf(S_ * (v[c] - maxv));

    float nll = __logf(s) + S_ * (maxv - vl);

    // Warp reduce, then cross-warp via smem, then one f64 atomic per block.
    #pragma unroll
    for (int o = 16; o > 0; o >>= 1)
        nll += __shfl_xor_sync(0xffffffffu, nll, o);

    __shared__ float warp_sums[8];  // 256 threads = 8 warps
    int lane = threadIdx.x & 31;
    int wid  = threadIdx.x >> 5;
    if (lane == 0) warp_sums[wid] = nll;
    __syncthreads();

    if (wid == 0) {
        float x = (lane < 8) ? warp_sums[lane] : 0.0f;
        #pragma unroll
        for (int o = 4; o > 0; o >>= 1)
            x += __shfl_xor_sync(0xffffffffu, x, o);
        if (lane == 0) atomicAdd(&g_loss, (double)x);
    }
}

// ---------------------------------------------------------------------------
// Kernel 4: finalize — mean over all pixels, write f32 scalar
// ---------------------------------------------------------------------------
__global__ void finalize_kernel(float* __restrict__ out) {
    out[0] = (float)(g_loss * (1.0 / (double)NPIX));
}

// ---------------------------------------------------------------------------
extern "C" void kernel_launch(void* const* d_in, const int* in_sizes, int n_in,
                              void* d_out, int out_size) {
    const float* pred   = (const float*)d_in[0];
    const int*   target = (const int*)d_in[1];
    float*       out    = (float*)d_out;

    init_kernel<<<1, 32>>>();
    hist_kernel<<<512, 256>>>(target);
    mlist_kernel<<<1, 32>>>();
    loss_kernel<<<NPIX / 256, 256>>>(pred, target);
    finalize_kernel<<<1, 1>>>(out);
}